// round 4
// baseline (speedup 1.0000x reference)
#include <cuda_runtime.h>

#define N_NODES 20000
#define N_EDGES 640000
#define D       128
#define NGRAPH  64

// ---------------- scratch (device globals; no allocation allowed) ----------
__device__ float g_Y [N_NODES * D];   // x @ W_rel^T   (then reused for layer2)
__device__ float g_H [N_NODES * D];   // x @ W_root^T + b, then += agg, relu -> h
__device__ float g_H2[N_NODES * D];   // layer-2 output
__device__ int   g_deg[N_NODES];
__device__ int   g_off[N_NODES + 1];
__device__ int   g_cur[N_NODES];
__device__ int   g_src[N_EDGES];
__device__ float g_w  [N_EDGES];

// ---------------- CSR build ------------------------------------------------
__global__ void k_zero() {
    int i = blockIdx.x * blockDim.x + threadIdx.x;
    if (i < N_NODES) g_deg[i] = 0;
}

__global__ void k_hist(const int* __restrict__ ei) {
    int e = blockIdx.x * blockDim.x + threadIdx.x;
    if (e < N_EDGES) atomicAdd(&g_deg[ei[N_EDGES + e]], 1);
}

__global__ void k_scan() {
    __shared__ int sums[1024];
    const int CH = 20;                       // 1024*20 = 20480 >= 20000
    int t = threadIdx.x;
    int base = t * CH;
    int local[CH];
    int s = 0;
    #pragma unroll
    for (int i = 0; i < CH; i++) {
        int idx = base + i;
        int v = (idx < N_NODES) ? g_deg[idx] : 0;
        local[i] = s;
        s += v;
    }
    sums[t] = s;
    __syncthreads();
    for (int d = 1; d < 1024; d <<= 1) {
        int v = 0;
        if (t >= d) v = sums[t - d];
        __syncthreads();
        if (t >= d) sums[t] += v;
        __syncthreads();
    }
    int off = (t == 0) ? 0 : sums[t - 1];
    #pragma unroll
    for (int i = 0; i < CH; i++) {
        int idx = base + i;
        if (idx < N_NODES) {
            int o = off + local[i];
            g_off[idx] = o;
            g_cur[idx] = o;
        }
    }
    if (t == 1023) g_off[N_NODES] = sums[1023];
}

__global__ void k_fill(const int* __restrict__ ei, const float* __restrict__ ew) {
    int e = blockIdx.x * blockDim.x + threadIdx.x;
    if (e < N_EDGES) {
        int dst = ei[N_EDGES + e];
        int p = atomicAdd(&g_cur[dst], 1);
        g_src[p] = ei[e];
        g_w[p]   = ew[e];
    }
}

// ---------------- GEMM: Out[i][c] = sum_k X[i][k]*W[c][k] (+bias[c]) -------
// BM=64 rows, BN=128 cols, BK=32; 256 threads; 4x8 register tile.
// MODE: 0 -> Out = g_Y; 1 -> Out = g_H; 2 -> Out = g_H2
template <int XSRC, int MODE>
__global__ void k_gemm(const float* __restrict__ Xext, const float* __restrict__ W,
                       const float* __restrict__ bias) {
    const float* X = (XSRC == 0) ? Xext : g_H;
    float* Out = (MODE == 0) ? g_Y : (MODE == 1 ? g_H : g_H2);

    __shared__ float Xs[64 * 32];
    __shared__ float Ws[128 * 36];          // +4 pad to break LDS conflicts
    int tid = threadIdx.x;
    int tx = tid & 15, ty = tid >> 4;
    int row0 = blockIdx.x * 64;

    float acc[4][8];
    #pragma unroll
    for (int r = 0; r < 4; r++)
        #pragma unroll
        for (int c = 0; c < 8; c++) acc[r][c] = 0.f;

    for (int kt = 0; kt < 4; kt++) {
        int k0 = kt * 32;
        for (int i = tid; i < 64 * 8; i += 256) {
            int r = i >> 3, kk = i & 7;
            int gr = row0 + r;
            float4 v = make_float4(0.f, 0.f, 0.f, 0.f);
            if (gr < N_NODES) v = *(const float4*)&X[gr * D + k0 + kk * 4];
            *(float4*)&Xs[r * 32 + kk * 4] = v;
        }
        for (int i = tid; i < 128 * 8; i += 256) {
            int c = i >> 3, kk = i & 7;
            float4 v = *(const float4*)&W[c * D + k0 + kk * 4];
            *(float4*)&Ws[c * 36 + kk * 4] = v;
        }
        __syncthreads();
        #pragma unroll
        for (int kk = 0; kk < 8; kk++) {
            float4 xv[4];
            #pragma unroll
            for (int r = 0; r < 4; r++)
                xv[r] = *(float4*)&Xs[(ty * 4 + r) * 32 + kk * 4];
            #pragma unroll
            for (int cc = 0; cc < 8; cc++) {
                float4 wv = *(float4*)&Ws[(cc * 16 + tx) * 36 + kk * 4];
                #pragma unroll
                for (int r = 0; r < 4; r++) {
                    acc[r][cc] += xv[r].x * wv.x;
                    acc[r][cc] += xv[r].y * wv.y;
                    acc[r][cc] += xv[r].z * wv.z;
                    acc[r][cc] += xv[r].w * wv.w;
                }
            }
        }
        __syncthreads();
    }
    #pragma unroll
    for (int cc = 0; cc < 8; cc++) {
        int c = cc * 16 + tx;
        float b = bias ? bias[c] : 0.f;
        #pragma unroll
        for (int r = 0; r < 4; r++) {
            int gr = row0 + ty * 4 + r;
            if (gr < N_NODES) Out[gr * D + c] = acc[r][cc] + b;
        }
    }
}

// ---------------- edge aggregation: H[i] += sum_e w_e * Y[src_e] -----------
// one warp per node; float4 per lane; 4-way unrolled for MLP
// MODE: 1 -> accumulate into g_H with relu; 2 -> accumulate into g_H2, no relu
template <int MODE>
__global__ void k_agg() {
    const float* Y = g_Y;
    float* H = (MODE == 1) ? g_H : g_H2;
    int node = (blockIdx.x * blockDim.x + threadIdx.x) >> 5;
    int lane = threadIdx.x & 31;
    if (node >= N_NODES) return;
    int beg = g_off[node], end = g_off[node + 1];
    float4 acc = *(float4*)&H[node * D + lane * 4];
    int e = beg;
    for (; e + 4 <= end; e += 4) {
        int s0 = g_src[e], s1 = g_src[e + 1], s2 = g_src[e + 2], s3 = g_src[e + 3];
        float w0 = g_w[e], w1 = g_w[e + 1], w2 = g_w[e + 2], w3 = g_w[e + 3];
        float4 v0 = *(const float4*)&Y[s0 * D + lane * 4];
        float4 v1 = *(const float4*)&Y[s1 * D + lane * 4];
        float4 v2 = *(const float4*)&Y[s2 * D + lane * 4];
        float4 v3 = *(const float4*)&Y[s3 * D + lane * 4];
        acc.x += w0 * v0.x; acc.y += w0 * v0.y; acc.z += w0 * v0.z; acc.w += w0 * v0.w;
        acc.x += w1 * v1.x; acc.y += w1 * v1.y; acc.z += w1 * v1.z; acc.w += w1 * v1.w;
        acc.x += w2 * v2.x; acc.y += w2 * v2.y; acc.z += w2 * v2.z; acc.w += w2 * v2.w;
        acc.x += w3 * v3.x; acc.y += w3 * v3.y; acc.z += w3 * v3.z; acc.w += w3 * v3.w;
    }
    for (; e < end; e++) {
        int s = g_src[e];
        float w = g_w[e];
        float4 v = *(const float4*)&Y[s * D + lane * 4];
        acc.x += w * v.x; acc.y += w * v.y; acc.z += w * v.z; acc.w += w * v.w;
    }
    if (MODE == 1) {
        acc.x = fmaxf(acc.x, 0.f); acc.y = fmaxf(acc.y, 0.f);
        acc.z = fmaxf(acc.z, 0.f); acc.w = fmaxf(acc.w, 0.f);
    }
    *(float4*)&H[node * D + lane * 4] = acc;
}

// ---------------- mean-pool (batch is sorted) + linear head + relu ---------
__global__ void k_pool(const int* __restrict__ batch,
                       const float* __restrict__ Wlin, const float* __restrict__ blin,
                       float* __restrict__ out) {
    const float* H2 = g_H2;
    int g = blockIdx.x;
    int c = threadIdx.x;   // 128 threads
    int lo = 0, hi = N_NODES;
    while (lo < hi) { int m = (lo + hi) >> 1; if (batch[m] < g) lo = m + 1; else hi = m; }
    int start = lo;
    lo = 0; hi = N_NODES;
    while (lo < hi) { int m = (lo + hi) >> 1; if (batch[m] < g + 1) lo = m + 1; else hi = m; }
    int end = lo;

    float acc = 0.f;
    for (int n = start; n < end; n++) acc += H2[n * D + c];
    float cnt = (float)(end - start);
    float pooled = acc / fmaxf(cnt, 1.f);
    float v = pooled * Wlin[c];

    __shared__ float red[128];
    red[c] = v;
    __syncthreads();
    for (int s = 64; s > 0; s >>= 1) {
        if (c < s) red[c] += red[c + s];
        __syncthreads();
    }
    if (c == 0) out[g] = fmaxf(red[0] + blin[0], 0.f);
}

// ---------------- launch ---------------------------------------------------
extern "C" void kernel_launch(void* const* d_in, const int* in_sizes, int n_in,
                              void* d_out, int out_size) {
    const float* x      = (const float*)d_in[0];
    const int*   ei     = (const int*)d_in[1];     // int32 (JAX x64 disabled)
    const int*   batch  = (const int*)d_in[2];     // int32
    const float* ew     = (const float*)d_in[3];
    const float* W1_rel = (const float*)d_in[4];
    const float* b1     = (const float*)d_in[5];
    const float* W1_root= (const float*)d_in[6];
    const float* W3_rel = (const float*)d_in[7];
    const float* b3     = (const float*)d_in[8];
    const float* W3_root= (const float*)d_in[9];
    const float* Wlin   = (const float*)d_in[10];
    const float* blin   = (const float*)d_in[11];
    float*       out    = (float*)d_out;

    // CSR build (reused by both layers)
    k_zero<<<(N_NODES + 255) / 256, 256>>>();
    k_hist<<<(N_EDGES + 255) / 256, 256>>>(ei);
    k_scan<<<1, 1024>>>();
    k_fill<<<(N_EDGES + 255) / 256, 256>>>(ei, ew);

    int gb = (N_NODES + 63) / 64;
    // layer 1: transform, then aggregate, relu
    k_gemm<0, 0><<<gb, 256>>>(x, W1_rel,  nullptr);   // Y  = x @ W1_rel^T
    k_gemm<0, 1><<<gb, 256>>>(x, W1_root, b1);        // H  = x @ W1_root^T + b1
    k_agg<1><<<(N_NODES * 32 + 255) / 256, 256>>>();  // H += agg(Y); relu

    // layer 2
    k_gemm<1, 0><<<gb, 256>>>(nullptr, W3_rel,  nullptr); // Y  = H @ W3_rel^T
    k_gemm<1, 2><<<gb, 256>>>(nullptr, W3_root, b3);      // H2 = H @ W3_root^T + b3
    k_agg<2><<<(N_NODES * 32 + 255) / 256, 256>>>();      // H2 += agg(Y)

    // pool + head
    k_pool<<<NGRAPH, 128>>>(batch, Wlin, blin, out);
}

// round 6
// speedup vs baseline: 1.0538x; 1.0538x over previous
#include <cuda_runtime.h>

#define N_NODES 20000
#define N_EDGES 640000
#define D       128
#define NGRAPH  64

// ---------------- scratch (device globals) ---------------------------------
__device__ float g_Y [N_NODES * D];
__device__ float g_H [N_NODES * D];
__device__ float g_H2[N_NODES * D];
__device__ int   g_deg[N_NODES];
__device__ int   g_off[N_NODES + 1];
__device__ int   g_cur[N_NODES];
__device__ int2  g_srcw[N_EDGES];       // packed (src, bit-cast weight)

// ---------------- CSR build ------------------------------------------------
__global__ void k_zero() {
    int i = blockIdx.x * blockDim.x + threadIdx.x;
    if (i < N_NODES) g_deg[i] = 0;
}

__global__ void k_hist(const int* __restrict__ ei) {
    int e = blockIdx.x * blockDim.x + threadIdx.x;
    if (e < N_EDGES) atomicAdd(&g_deg[ei[N_EDGES + e]], 1);
}

__global__ void k_scan() {
    __shared__ int sums[1024];
    const int CH = 20;
    int t = threadIdx.x;
    int base = t * CH;
    int local[CH];
    int s = 0;
    #pragma unroll
    for (int i = 0; i < CH; i++) {
        int idx = base + i;
        int v = (idx < N_NODES) ? g_deg[idx] : 0;
        local[i] = s;
        s += v;
    }
    sums[t] = s;
    __syncthreads();
    for (int d = 1; d < 1024; d <<= 1) {
        int v = 0;
        if (t >= d) v = sums[t - d];
        __syncthreads();
        if (t >= d) sums[t] += v;
        __syncthreads();
    }
    int off = (t == 0) ? 0 : sums[t - 1];
    #pragma unroll
    for (int i = 0; i < CH; i++) {
        int idx = base + i;
        if (idx < N_NODES) {
            int o = off + local[i];
            g_off[idx] = o;
            g_cur[idx] = o;
        }
    }
    if (t == 1023) g_off[N_NODES] = sums[1023];
}

__global__ void k_fill(const int* __restrict__ ei, const float* __restrict__ ew) {
    int e = blockIdx.x * blockDim.x + threadIdx.x;
    if (e < N_EDGES) {
        int dst = ei[N_EDGES + e];
        int p = atomicAdd(&g_cur[dst], 1);
        g_srcw[p] = make_int2(ei[e], __float_as_int(ew[e]));
    }
}

// ---------------- fused dual GEMM with packed f32x2 FFMA -------------------
// Ya[i][c] = sum_k X[i][k]*Wa[c][k]
// Yb[i][c] = sum_k X[i][k]*Wb[c][k] + bias[c]
__device__ __forceinline__ void ffma2(unsigned long long& d,
                                      unsigned long long a,
                                      unsigned long long b) {
    asm("fma.rn.f32x2 %0, %1, %2, %0;" : "+l"(d) : "l"(a), "l"(b));
}
__device__ __forceinline__ unsigned long long bcast2(float x) {
    unsigned long long r;
    asm("mov.b64 %0, {%1, %1};" : "=l"(r) : "f"(x));
    return r;
}

template <int LAYER>   // 0: x -> (g_Y, g_H) | 1: g_H -> (g_Y, g_H2)
__global__ void k_gemm2(const float* __restrict__ Xext,
                        const float* __restrict__ Wa,
                        const float* __restrict__ Wb,
                        const float* __restrict__ bias) {
    const float* X  = (LAYER == 0) ? Xext : g_H;
    float* Ya = g_Y;
    float* Yb = (LAYER == 0) ? g_H : g_H2;

    __shared__ float Xs [64 * 33];        // [row][k], stride 33
    __shared__ float Was[32 * 128];       // [k][c]
    __shared__ float Wbs[32 * 128];       // [k][c]

    int tid = threadIdx.x;
    int tx = tid & 15, ty = tid >> 4;
    int row0 = blockIdx.x * 64;

    unsigned long long accA[4][4], accB[4][4];   // [r][colpair]
    #pragma unroll
    for (int r = 0; r < 4; r++)
        #pragma unroll
        for (int p = 0; p < 4; p++) { accA[r][p] = 0ull; accB[r][p] = 0ull; }

    for (int kt = 0; kt < 4; kt++) {
        int k0 = kt * 32;
        // X tile: 64 rows x 8 float4 (row-major)
        for (int i = tid; i < 64 * 8; i += 256) {
            int r = i >> 3, kk = i & 7;
            int gr = row0 + r;
            float4 v = make_float4(0.f, 0.f, 0.f, 0.f);
            if (gr < N_NODES) v = *(const float4*)&X[gr * D + k0 + kk * 4];
            Xs[r * 33 + kk * 4 + 0] = v.x;
            Xs[r * 33 + kk * 4 + 1] = v.y;
            Xs[r * 33 + kk * 4 + 2] = v.z;
            Xs[r * 33 + kk * 4 + 3] = v.w;
        }
        // W tiles transposed into k-major smem: each thread does 4 float4 per matrix
        {
            int c = tid & 127, half = tid >> 7;       // half in {0,1}
            #pragma unroll
            for (int q = 0; q < 4; q++) {
                int kk4 = half * 4 + q;               // 0..7 covers the full 32-k slice
                float4 va = *(const float4*)&Wa[c * D + k0 + kk4 * 4];
                float4 vb = *(const float4*)&Wb[c * D + k0 + kk4 * 4];
                Was[(kk4 * 4 + 0) * 128 + c] = va.x;
                Was[(kk4 * 4 + 1) * 128 + c] = va.y;
                Was[(kk4 * 4 + 2) * 128 + c] = va.z;
                Was[(kk4 * 4 + 3) * 128 + c] = va.w;
                Wbs[(kk4 * 4 + 0) * 128 + c] = vb.x;
                Wbs[(kk4 * 4 + 1) * 128 + c] = vb.y;
                Wbs[(kk4 * 4 + 2) * 128 + c] = vb.z;
                Wbs[(kk4 * 4 + 3) * 128 + c] = vb.w;
            }
        }
        __syncthreads();

        #pragma unroll 8
        for (int kk = 0; kk < 32; kk++) {
            unsigned long long xx[4];
            #pragma unroll
            for (int r = 0; r < 4; r++)
                xx[r] = bcast2(Xs[(ty * 4 + r) * 33 + kk]);
            #pragma unroll
            for (int p = 0; p < 4; p++) {
                unsigned long long wa = *(const unsigned long long*)&Was[kk * 128 + 32 * p + 2 * tx];
                unsigned long long wb = *(const unsigned long long*)&Wbs[kk * 128 + 32 * p + 2 * tx];
                #pragma unroll
                for (int r = 0; r < 4; r++) {
                    ffma2(accA[r][p], xx[r], wa);
                    ffma2(accB[r][p], xx[r], wb);
                }
            }
        }
        __syncthreads();
    }

    #pragma unroll
    for (int p = 0; p < 4; p++) {
        int c = 32 * p + 2 * tx;
        float b0 = bias[c], b1 = bias[c + 1];
        #pragma unroll
        for (int r = 0; r < 4; r++) {
            int gr = row0 + ty * 4 + r;
            if (gr < N_NODES) {
                float a0, a1;
                asm("mov.b64 {%0, %1}, %2;" : "=f"(a0), "=f"(a1) : "l"(accA[r][p]));
                *(float2*)&Ya[gr * D + c] = make_float2(a0, a1);
                asm("mov.b64 {%0, %1}, %2;" : "=f"(a0), "=f"(a1) : "l"(accB[r][p]));
                *(float2*)&Yb[gr * D + c] = make_float2(a0 + b0, a1 + b1);
            }
        }
    }
}

// ---------------- edge aggregation: H[i] += sum_e w_e * Y[src_e] -----------
template <int MODE>   // 1: into g_H with relu; 2: into g_H2
__global__ void k_agg() {
    const float* Y = g_Y;
    float* H = (MODE == 1) ? g_H : g_H2;
    int node = (blockIdx.x * blockDim.x + threadIdx.x) >> 5;
    int lane = threadIdx.x & 31;
    if (node >= N_NODES) return;
    int beg = g_off[node], end = g_off[node + 1];
    float4 acc = *(float4*)&H[node * D + lane * 4];
    int e = beg;
    for (; e + 4 <= end; e += 4) {
        int2 p0 = g_srcw[e],     p1 = g_srcw[e + 1];
        int2 p2 = g_srcw[e + 2], p3 = g_srcw[e + 3];
        float w0 = __int_as_float(p0.y), w1 = __int_as_float(p1.y);
        float w2 = __int_as_float(p2.y), w3 = __int_as_float(p3.y);
        float4 v0 = *(const float4*)&Y[p0.x * D + lane * 4];
        float4 v1 = *(const float4*)&Y[p1.x * D + lane * 4];
        float4 v2 = *(const float4*)&Y[p2.x * D + lane * 4];
        float4 v3 = *(const float4*)&Y[p3.x * D + lane * 4];
        acc.x += w0 * v0.x; acc.y += w0 * v0.y; acc.z += w0 * v0.z; acc.w += w0 * v0.w;
        acc.x += w1 * v1.x; acc.y += w1 * v1.y; acc.z += w1 * v1.z; acc.w += w1 * v1.w;
        acc.x += w2 * v2.x; acc.y += w2 * v2.y; acc.z += w2 * v2.z; acc.w += w2 * v2.w;
        acc.x += w3 * v3.x; acc.y += w3 * v3.y; acc.z += w3 * v3.z; acc.w += w3 * v3.w;
    }
    for (; e < end; e++) {
        int2 pe = g_srcw[e];
        float w = __int_as_float(pe.y);
        float4 v = *(const float4*)&Y[pe.x * D + lane * 4];
        acc.x += w * v.x; acc.y += w * v.y; acc.z += w * v.z; acc.w += w * v.w;
    }
    if (MODE == 1) {
        acc.x = fmaxf(acc.x, 0.f); acc.y = fmaxf(acc.y, 0.f);
        acc.z = fmaxf(acc.z, 0.f); acc.w = fmaxf(acc.w, 0.f);
    }
    *(float4*)&H[node * D + lane * 4] = acc;
}

// ---------------- mean-pool + linear head + relu ---------------------------
__global__ void k_pool(const int* __restrict__ batch,
                       const float* __restrict__ Wlin, const float* __restrict__ blin,
                       float* __restrict__ out) {
    const float* H2 = g_H2;
    int g = blockIdx.x;
    int c = threadIdx.x;   // 128 threads
    int lo = 0, hi = N_NODES;
    while (lo < hi) { int m = (lo + hi) >> 1; if (batch[m] < g) lo = m + 1; else hi = m; }
    int start = lo;
    lo = 0; hi = N_NODES;
    while (lo < hi) { int m = (lo + hi) >> 1; if (batch[m] < g + 1) lo = m + 1; else hi = m; }
    int end = lo;

    float acc = 0.f;
    for (int n = start; n < end; n++) acc += H2[n * D + c];
    float cnt = (float)(end - start);
    float pooled = acc / fmaxf(cnt, 1.f);
    float v = pooled * Wlin[c];

    __shared__ float red[128];
    red[c] = v;
    __syncthreads();
    for (int s = 64; s > 0; s >>= 1) {
        if (c < s) red[c] += red[c + s];
        __syncthreads();
    }
    if (c == 0) out[g] = fmaxf(red[0] + blin[0], 0.f);
}

// ---------------- launch ---------------------------------------------------
extern "C" void kernel_launch(void* const* d_in, const int* in_sizes, int n_in,
                              void* d_out, int out_size) {
    const float* x      = (const float*)d_in[0];
    const int*   ei     = (const int*)d_in[1];
    const int*   batch  = (const int*)d_in[2];
    const float* ew     = (const float*)d_in[3];
    const float* W1_rel = (const float*)d_in[4];
    const float* b1     = (const float*)d_in[5];
    const float* W1_root= (const float*)d_in[6];
    const float* W3_rel = (const float*)d_in[7];
    const float* b3     = (const float*)d_in[8];
    const float* W3_root= (const float*)d_in[9];
    const float* Wlin   = (const float*)d_in[10];
    const float* blin   = (const float*)d_in[11];
    float*       out    = (float*)d_out;

    // CSR build
    k_zero<<<(N_NODES + 255) / 256, 256>>>();
    k_hist<<<(N_EDGES + 255) / 256, 256>>>(ei);
    k_scan<<<1, 1024>>>();
    k_fill<<<(N_EDGES + 255) / 256, 256>>>(ei, ew);

    int gb = (N_NODES + 63) / 64;
    // layer 1
    k_gemm2<0><<<gb, 256>>>(x, W1_rel, W1_root, b1);
    k_agg<1><<<(N_NODES * 32 + 255) / 256, 256>>>();

    // layer 2
    k_gemm2<1><<<gb, 256>>>(nullptr, W3_rel, W3_root, b3);
    k_agg<2><<<(N_NODES * 32 + 255) / 256, 256>>>();

    // pool + head
    k_pool<<<NGRAPH, 128>>>(batch, Wlin, blin, out);
}

// round 7
// speedup vs baseline: 1.0693x; 1.0147x over previous
#include <cuda_runtime.h>

#define N_NODES 20000
#define N_EDGES 640000
#define D       128
#define NGRAPH  64

// ---------------- scratch (device globals) ---------------------------------
__device__ float g_Y [N_NODES * D];
__device__ float g_H [N_NODES * D];
__device__ float g_H2[N_NODES * D];
__device__ int   g_deg[N_NODES];
__device__ int   g_off[N_NODES + 1];
__device__ int   g_cur[N_NODES];
__device__ int2  g_srcw[N_EDGES];       // packed (src, bit-cast weight)

// ---------------- CSR build ------------------------------------------------
__global__ void k_zero() {
    int i = blockIdx.x * blockDim.x + threadIdx.x;
    if (i < N_NODES) g_deg[i] = 0;
}

// 4 edges/thread: 4 independent atomics in flight
__global__ void k_hist(const int* __restrict__ ei) {
    int e0 = (blockIdx.x * blockDim.x + threadIdx.x) * 4;
    if (e0 < N_EDGES) {
        int4 d = *(const int4*)&ei[N_EDGES + e0];
        atomicAdd(&g_deg[d.x], 1);
        atomicAdd(&g_deg[d.y], 1);
        atomicAdd(&g_deg[d.z], 1);
        atomicAdd(&g_deg[d.w], 1);
    }
}

__global__ void k_scan() {
    __shared__ int sums[1024];
    const int CH = 20;
    int t = threadIdx.x;
    int base = t * CH;
    int local[CH];
    int s = 0;
    #pragma unroll
    for (int i = 0; i < CH; i++) {
        int idx = base + i;
        int v = (idx < N_NODES) ? g_deg[idx] : 0;
        local[i] = s;
        s += v;
    }
    sums[t] = s;
    __syncthreads();
    for (int d = 1; d < 1024; d <<= 1) {
        int v = 0;
        if (t >= d) v = sums[t - d];
        __syncthreads();
        if (t >= d) sums[t] += v;
        __syncthreads();
    }
    int off = (t == 0) ? 0 : sums[t - 1];
    #pragma unroll
    for (int i = 0; i < CH; i++) {
        int idx = base + i;
        if (idx < N_NODES) {
            int o = off + local[i];
            g_off[idx] = o;
            g_cur[idx] = o;
        }
    }
    if (t == 1023) g_off[N_NODES] = sums[1023];
}

// 4 edges/thread: batch loads, 4 atomics in flight, then 4 stores
__global__ void k_fill(const int* __restrict__ ei, const float* __restrict__ ew) {
    int e0 = (blockIdx.x * blockDim.x + threadIdx.x) * 4;
    if (e0 < N_EDGES) {
        int4   dd = *(const int4*)&ei[N_EDGES + e0];
        int4   ss = *(const int4*)&ei[e0];
        float4 ww = *(const float4*)&ew[e0];
        int p0 = atomicAdd(&g_cur[dd.x], 1);
        int p1 = atomicAdd(&g_cur[dd.y], 1);
        int p2 = atomicAdd(&g_cur[dd.z], 1);
        int p3 = atomicAdd(&g_cur[dd.w], 1);
        g_srcw[p0] = make_int2(ss.x, __float_as_int(ww.x));
        g_srcw[p1] = make_int2(ss.y, __float_as_int(ww.y));
        g_srcw[p2] = make_int2(ss.z, __float_as_int(ww.z));
        g_srcw[p3] = make_int2(ss.w, __float_as_int(ww.w));
    }
}

// ---------------- fused dual GEMM with packed f32x2 FFMA -------------------
__device__ __forceinline__ void ffma2(unsigned long long& d,
                                      unsigned long long a,
                                      unsigned long long b) {
    asm("fma.rn.f32x2 %0, %1, %2, %0;" : "+l"(d) : "l"(a), "l"(b));
}
__device__ __forceinline__ unsigned long long bcast2(float x) {
    unsigned long long r;
    asm("mov.b64 %0, {%1, %1};" : "=l"(r) : "f"(x));
    return r;
}

#define XS_STRIDE 36

template <int LAYER>   // 0: x -> (g_Y, g_H) | 1: g_H -> (g_Y, g_H2)
__global__ void __launch_bounds__(256, 2)
k_gemm2(const float* __restrict__ Xext,
        const float* __restrict__ Wa,
        const float* __restrict__ Wb,
        const float* __restrict__ bias) {
    const float* X  = (LAYER == 0) ? Xext : g_H;
    float* Ya = g_Y;
    float* Yb = (LAYER == 0) ? g_H : g_H2;

    __shared__ float Xs [64 * XS_STRIDE];   // [row][k]
    __shared__ float Was[32 * 128];         // [k][c]
    __shared__ float Wbs[32 * 128];         // [k][c]

    int tid = threadIdx.x;
    int tx = tid & 15, ty = tid >> 4;
    int row0 = blockIdx.x * 64;

    unsigned long long accA[4][4], accB[4][4];   // [r][colpair]
    #pragma unroll
    for (int r = 0; r < 4; r++)
        #pragma unroll
        for (int p = 0; p < 4; p++) { accA[r][p] = 0ull; accB[r][p] = 0ull; }

    for (int kt = 0; kt < 4; kt++) {
        int k0 = kt * 32;
        // X tile: 64 rows x 8 float4 (row-major, stride 36 keeps 16B align)
        for (int i = tid; i < 64 * 8; i += 256) {
            int r = i >> 3, kk = i & 7;
            int gr = row0 + r;
            float4 v = make_float4(0.f, 0.f, 0.f, 0.f);
            if (gr < N_NODES) v = *(const float4*)&X[gr * D + k0 + kk * 4];
            *(float4*)&Xs[r * XS_STRIDE + kk * 4] = v;
        }
        // W tiles transposed into k-major smem
        {
            int c = tid & 127, half = tid >> 7;
            #pragma unroll
            for (int q = 0; q < 4; q++) {
                int kk4 = half * 4 + q;               // 0..7 covers full 32-k slice
                float4 va = *(const float4*)&Wa[c * D + k0 + kk4 * 4];
                float4 vb = *(const float4*)&Wb[c * D + k0 + kk4 * 4];
                Was[(kk4 * 4 + 0) * 128 + c] = va.x;
                Was[(kk4 * 4 + 1) * 128 + c] = va.y;
                Was[(kk4 * 4 + 2) * 128 + c] = va.z;
                Was[(kk4 * 4 + 3) * 128 + c] = va.w;
                Wbs[(kk4 * 4 + 0) * 128 + c] = vb.x;
                Wbs[(kk4 * 4 + 1) * 128 + c] = vb.y;
                Wbs[(kk4 * 4 + 2) * 128 + c] = vb.z;
                Wbs[(kk4 * 4 + 3) * 128 + c] = vb.w;
            }
        }
        __syncthreads();

        #pragma unroll
        for (int kk4 = 0; kk4 < 8; kk4++) {
            float4 xr[4];
            #pragma unroll
            for (int r = 0; r < 4; r++)
                xr[r] = *(float4*)&Xs[(ty * 4 + r) * XS_STRIDE + kk4 * 4];

            #define K_STEP(J, COMP)                                                        \
            {                                                                              \
                int kk = kk4 * 4 + J;                                                      \
                unsigned long long xx[4];                                                  \
                xx[0] = bcast2(xr[0].COMP); xx[1] = bcast2(xr[1].COMP);                    \
                xx[2] = bcast2(xr[2].COMP); xx[3] = bcast2(xr[3].COMP);                    \
                _Pragma("unroll")                                                          \
                for (int p = 0; p < 4; p++) {                                              \
                    unsigned long long wa = *(const unsigned long long*)&Was[kk * 128 + 32 * p + 2 * tx]; \
                    unsigned long long wb = *(const unsigned long long*)&Wbs[kk * 128 + 32 * p + 2 * tx]; \
                    _Pragma("unroll")                                                      \
                    for (int r = 0; r < 4; r++) {                                          \
                        ffma2(accA[r][p], xx[r], wa);                                      \
                        ffma2(accB[r][p], xx[r], wb);                                      \
                    }                                                                      \
                }                                                                          \
            }
            K_STEP(0, x)
            K_STEP(1, y)
            K_STEP(2, z)
            K_STEP(3, w)
            #undef K_STEP
        }
        __syncthreads();
    }

    #pragma unroll
    for (int p = 0; p < 4; p++) {
        int c = 32 * p + 2 * tx;
        float b0 = bias[c], b1 = bias[c + 1];
        #pragma unroll
        for (int r = 0; r < 4; r++) {
            int gr = row0 + ty * 4 + r;
            if (gr < N_NODES) {
                float a0, a1;
                asm("mov.b64 {%0, %1}, %2;" : "=f"(a0), "=f"(a1) : "l"(accA[r][p]));
                *(float2*)&Ya[gr * D + c] = make_float2(a0, a1);
                asm("mov.b64 {%0, %1}, %2;" : "=f"(a0), "=f"(a1) : "l"(accB[r][p]));
                *(float2*)&Yb[gr * D + c] = make_float2(a0 + b0, a1 + b1);
            }
        }
    }
}

// ---------------- edge aggregation: H[i] += sum_e w_e * Y[src_e] -----------
template <int MODE>   // 1: into g_H with relu; 2: into g_H2
__global__ void k_agg() {
    const float* Y = g_Y;
    float* H = (MODE == 1) ? g_H : g_H2;
    int node = (blockIdx.x * blockDim.x + threadIdx.x) >> 5;
    int lane = threadIdx.x & 31;
    if (node >= N_NODES) return;
    int beg = g_off[node], end = g_off[node + 1];
    float4 acc = *(float4*)&H[node * D + lane * 4];
    int e = beg;
    // 8-edge unroll: ~40 outstanding loads per warp
    for (; e + 8 <= end; e += 8) {
        int2 p[8];
        #pragma unroll
        for (int j = 0; j < 8; j++) p[j] = g_srcw[e + j];
        float4 v[8];
        #pragma unroll
        for (int j = 0; j < 8; j++) v[j] = *(const float4*)&Y[p[j].x * D + lane * 4];
        #pragma unroll
        for (int j = 0; j < 8; j++) {
            float w = __int_as_float(p[j].y);
            acc.x += w * v[j].x; acc.y += w * v[j].y;
            acc.z += w * v[j].z; acc.w += w * v[j].w;
        }
    }
    for (; e < end; e++) {
        int2 pe = g_srcw[e];
        float w = __int_as_float(pe.y);
        float4 v = *(const float4*)&Y[pe.x * D + lane * 4];
        acc.x += w * v.x; acc.y += w * v.y; acc.z += w * v.z; acc.w += w * v.w;
    }
    if (MODE == 1) {
        acc.x = fmaxf(acc.x, 0.f); acc.y = fmaxf(acc.y, 0.f);
        acc.z = fmaxf(acc.z, 0.f); acc.w = fmaxf(acc.w, 0.f);
    }
    *(float4*)&H[node * D + lane * 4] = acc;
}

// ---------------- mean-pool + linear head + relu ---------------------------
__global__ void k_pool(const int* __restrict__ batch,
                       const float* __restrict__ Wlin, const float* __restrict__ blin,
                       float* __restrict__ out) {
    const float* H2 = g_H2;
    int g = blockIdx.x;
    int c = threadIdx.x;   // 128 threads
    int lo = 0, hi = N_NODES;
    while (lo < hi) { int m = (lo + hi) >> 1; if (batch[m] < g) lo = m + 1; else hi = m; }
    int start = lo;
    lo = 0; hi = N_NODES;
    while (lo < hi) { int m = (lo + hi) >> 1; if (batch[m] < g + 1) lo = m + 1; else hi = m; }
    int end = lo;

    float acc = 0.f;
    for (int n = start; n < end; n++) acc += H2[n * D + c];
    float cnt = (float)(end - start);
    float pooled = acc / fmaxf(cnt, 1.f);
    float v = pooled * Wlin[c];

    __shared__ float red[128];
    red[c] = v;
    __syncthreads();
    for (int s = 64; s > 0; s >>= 1) {
        if (c < s) red[c] += red[c + s];
        __syncthreads();
    }
    if (c == 0) out[g] = fmaxf(red[0] + blin[0], 0.f);
}

// ---------------- launch ---------------------------------------------------
extern "C" void kernel_launch(void* const* d_in, const int* in_sizes, int n_in,
                              void* d_out, int out_size) {
    const float* x      = (const float*)d_in[0];
    const int*   ei     = (const int*)d_in[1];
    const int*   batch  = (const int*)d_in[2];
    const float* ew     = (const float*)d_in[3];
    const float* W1_rel = (const float*)d_in[4];
    const float* b1     = (const float*)d_in[5];
    const float* W1_root= (const float*)d_in[6];
    const float* W3_rel = (const float*)d_in[7];
    const float* b3     = (const float*)d_in[8];
    const float* W3_root= (const float*)d_in[9];
    const float* Wlin   = (const float*)d_in[10];
    const float* blin   = (const float*)d_in[11];
    float*       out    = (float*)d_out;

    // CSR build
    k_zero<<<(N_NODES + 255) / 256, 256>>>();
    k_hist<<<(N_EDGES / 4 + 255) / 256, 256>>>(ei);
    k_scan<<<1, 1024>>>();
    k_fill<<<(N_EDGES / 4 + 255) / 256, 256>>>(ei, ew);

    int gb = (N_NODES + 63) / 64;
    // layer 1
    k_gemm2<0><<<gb, 256>>>(x, W1_rel, W1_root, b1);
    k_agg<1><<<(N_NODES * 32 + 255) / 256, 256>>>();

    // layer 2
    k_gemm2<1><<<gb, 256>>>(nullptr, W3_rel, W3_root, b3);
    k_agg<2><<<(N_NODES * 32 + 255) / 256, 256>>>();

    // pool + head
    k_pool<<<NGRAPH, 128>>>(batch, Wlin, blin, out);
}

// round 8
// speedup vs baseline: 1.1456x; 1.0714x over previous
#include <cuda_runtime.h>

#define N_NODES 20000
#define N_EDGES 640000
#define D       128
#define NGRAPH  64

// ---------------- scratch (device globals) ---------------------------------
__device__ float g_Y [N_NODES * D];
__device__ float g_H [N_NODES * D];
__device__ float g_H2[N_NODES * D];
__device__ int   g_deg[N_NODES];
__device__ int   g_off[N_NODES + 1];
__device__ int   g_rank[N_EDGES];       // rank of edge within its dst bucket
__device__ int2  g_srcw[N_EDGES];       // packed (src, bit-cast weight)

// ---------------- CSR build ------------------------------------------------
__global__ void k_zero() {
    int i = blockIdx.x * blockDim.x + threadIdx.x;
    if (i < N_NODES) g_deg[i] = 0;
}

// 1 edge/thread (max warp count hides ATOMG latency); rank captured here
__global__ void k_hist(const int* __restrict__ ei) {
    int e = blockIdx.x * blockDim.x + threadIdx.x;
    if (e < N_EDGES) {
        int dst = ei[N_EDGES + e];
        g_rank[e] = atomicAdd(&g_deg[dst], 1);
    }
}

__global__ void k_scan() {
    __shared__ int sums[1024];
    const int CH = 20;
    int t = threadIdx.x;
    int base = t * CH;
    int local[CH];
    int s = 0;
    #pragma unroll
    for (int i = 0; i < CH; i++) {
        int idx = base + i;
        int v = (idx < N_NODES) ? g_deg[idx] : 0;
        local[i] = s;
        s += v;
    }
    sums[t] = s;
    __syncthreads();
    for (int d = 1; d < 1024; d <<= 1) {
        int v = 0;
        if (t >= d) v = sums[t - d];
        __syncthreads();
        if (t >= d) sums[t] += v;
        __syncthreads();
    }
    int off = (t == 0) ? 0 : sums[t - 1];
    #pragma unroll
    for (int i = 0; i < CH; i++) {
        int idx = base + i;
        if (idx < N_NODES) g_off[idx] = off + local[i];
    }
    if (t == 1023) g_off[N_NODES] = sums[1023];
}

// atomic-free scatter: p = off[dst] + rank[e]; 4 edges/thread for MLP
__global__ void k_place(const int* __restrict__ ei, const float* __restrict__ ew) {
    int e0 = (blockIdx.x * blockDim.x + threadIdx.x) * 4;
    if (e0 < N_EDGES) {
        int4   dd = *(const int4*)&ei[N_EDGES + e0];
        int4   ss = *(const int4*)&ei[e0];
        float4 ww = *(const float4*)&ew[e0];
        int4   rr = *(const int4*)&g_rank[e0];
        int p0 = g_off[dd.x] + rr.x;
        int p1 = g_off[dd.y] + rr.y;
        int p2 = g_off[dd.z] + rr.z;
        int p3 = g_off[dd.w] + rr.w;
        g_srcw[p0] = make_int2(ss.x, __float_as_int(ww.x));
        g_srcw[p1] = make_int2(ss.y, __float_as_int(ww.y));
        g_srcw[p2] = make_int2(ss.z, __float_as_int(ww.z));
        g_srcw[p3] = make_int2(ss.w, __float_as_int(ww.w));
    }
}

// ---------------- fused dual GEMM with packed f32x2 FFMA -------------------
__device__ __forceinline__ void ffma2(unsigned long long& d,
                                      unsigned long long a,
                                      unsigned long long b) {
    asm("fma.rn.f32x2 %0, %1, %2, %0;" : "+l"(d) : "l"(a), "l"(b));
}
__device__ __forceinline__ unsigned long long bcast2(float x) {
    unsigned long long r;
    asm("mov.b64 %0, {%1, %1};" : "=l"(r) : "f"(x));
    return r;
}

#define XS_STRIDE 36

template <int LAYER>   // 0: x -> (g_Y, g_H) | 1: g_H -> (g_Y, g_H2)
__global__ void __launch_bounds__(256, 2)
k_gemm2(const float* __restrict__ Xext,
        const float* __restrict__ Wa,
        const float* __restrict__ Wb,
        const float* __restrict__ bias) {
    const float* X  = (LAYER == 0) ? Xext : g_H;
    float* Ya = g_Y;
    float* Yb = (LAYER == 0) ? g_H : g_H2;

    __shared__ float Xs [64 * XS_STRIDE];   // [row][k]
    __shared__ float Was[32 * 128];         // [k][c]
    __shared__ float Wbs[32 * 128];         // [k][c]

    int tid = threadIdx.x;
    int tx = tid & 15, ty = tid >> 4;
    int row0 = blockIdx.x * 64;

    unsigned long long accA[4][4], accB[4][4];   // [r][colpair]
    #pragma unroll
    for (int r = 0; r < 4; r++)
        #pragma unroll
        for (int p = 0; p < 4; p++) { accA[r][p] = 0ull; accB[r][p] = 0ull; }

    for (int kt = 0; kt < 4; kt++) {
        int k0 = kt * 32;
        for (int i = tid; i < 64 * 8; i += 256) {
            int r = i >> 3, kk = i & 7;
            int gr = row0 + r;
            float4 v = make_float4(0.f, 0.f, 0.f, 0.f);
            if (gr < N_NODES) v = *(const float4*)&X[gr * D + k0 + kk * 4];
            *(float4*)&Xs[r * XS_STRIDE + kk * 4] = v;
        }
        {
            int c = tid & 127, half = tid >> 7;
            #pragma unroll
            for (int q = 0; q < 4; q++) {
                int kk4 = half * 4 + q;               // 0..7 covers full 32-k slice
                float4 va = *(const float4*)&Wa[c * D + k0 + kk4 * 4];
                float4 vb = *(const float4*)&Wb[c * D + k0 + kk4 * 4];
                Was[(kk4 * 4 + 0) * 128 + c] = va.x;
                Was[(kk4 * 4 + 1) * 128 + c] = va.y;
                Was[(kk4 * 4 + 2) * 128 + c] = va.z;
                Was[(kk4 * 4 + 3) * 128 + c] = va.w;
                Wbs[(kk4 * 4 + 0) * 128 + c] = vb.x;
                Wbs[(kk4 * 4 + 1) * 128 + c] = vb.y;
                Wbs[(kk4 * 4 + 2) * 128 + c] = vb.z;
                Wbs[(kk4 * 4 + 3) * 128 + c] = vb.w;
            }
        }
        __syncthreads();

        #pragma unroll
        for (int kk4 = 0; kk4 < 8; kk4++) {
            float4 xr[4];
            #pragma unroll
            for (int r = 0; r < 4; r++)
                xr[r] = *(float4*)&Xs[(ty * 4 + r) * XS_STRIDE + kk4 * 4];

            #define K_STEP(J, COMP)                                                        \
            {                                                                              \
                int kk = kk4 * 4 + J;                                                      \
                unsigned long long xx[4];                                                  \
                xx[0] = bcast2(xr[0].COMP); xx[1] = bcast2(xr[1].COMP);                    \
                xx[2] = bcast2(xr[2].COMP); xx[3] = bcast2(xr[3].COMP);                    \
                _Pragma("unroll")                                                          \
                for (int p = 0; p < 4; p++) {                                              \
                    unsigned long long wa = *(const unsigned long long*)&Was[kk * 128 + 32 * p + 2 * tx]; \
                    unsigned long long wb = *(const unsigned long long*)&Wbs[kk * 128 + 32 * p + 2 * tx]; \
                    _Pragma("unroll")                                                      \
                    for (int r = 0; r < 4; r++) {                                          \
                        ffma2(accA[r][p], xx[r], wa);                                      \
                        ffma2(accB[r][p], xx[r], wb);                                      \
                    }                                                                      \
                }                                                                          \
            }
            K_STEP(0, x)
            K_STEP(1, y)
            K_STEP(2, z)
            K_STEP(3, w)
            #undef K_STEP
        }
        __syncthreads();
    }

    #pragma unroll
    for (int p = 0; p < 4; p++) {
        int c = 32 * p + 2 * tx;
        float b0 = bias[c], b1 = bias[c + 1];
        #pragma unroll
        for (int r = 0; r < 4; r++) {
            int gr = row0 + ty * 4 + r;
            if (gr < N_NODES) {
                float a0, a1;
                asm("mov.b64 {%0, %1}, %2;" : "=f"(a0), "=f"(a1) : "l"(accA[r][p]));
                *(float2*)&Ya[gr * D + c] = make_float2(a0, a1);
                asm("mov.b64 {%0, %1}, %2;" : "=f"(a0), "=f"(a1) : "l"(accB[r][p]));
                *(float2*)&Yb[gr * D + c] = make_float2(a0 + b0, a1 + b1);
            }
        }
    }
}

// ---------------- edge aggregation: H[i] += sum_e w_e * Y[src_e] -----------
template <int MODE>   // 1: into g_H with relu; 2: into g_H2
__global__ void k_agg() {
    const float* Y = g_Y;
    float* H = (MODE == 1) ? g_H : g_H2;
    int node = (blockIdx.x * blockDim.x + threadIdx.x) >> 5;
    int lane = threadIdx.x & 31;
    if (node >= N_NODES) return;
    int beg = g_off[node], end = g_off[node + 1];
    float4 acc = *(float4*)&H[node * D + lane * 4];
    int e = beg;
    for (; e + 8 <= end; e += 8) {
        int2 p[8];
        #pragma unroll
        for (int j = 0; j < 8; j++) p[j] = g_srcw[e + j];
        float4 v[8];
        #pragma unroll
        for (int j = 0; j < 8; j++) v[j] = *(const float4*)&Y[p[j].x * D + lane * 4];
        #pragma unroll
        for (int j = 0; j < 8; j++) {
            float w = __int_as_float(p[j].y);
            acc.x += w * v[j].x; acc.y += w * v[j].y;
            acc.z += w * v[j].z; acc.w += w * v[j].w;
        }
    }
    for (; e < end; e++) {
        int2 pe = g_srcw[e];
        float w = __int_as_float(pe.y);
        float4 v = *(const float4*)&Y[pe.x * D + lane * 4];
        acc.x += w * v.x; acc.y += w * v.y; acc.z += w * v.z; acc.w += w * v.w;
    }
    if (MODE == 1) {
        acc.x = fmaxf(acc.x, 0.f); acc.y = fmaxf(acc.y, 0.f);
        acc.z = fmaxf(acc.z, 0.f); acc.w = fmaxf(acc.w, 0.f);
    }
    *(float4*)&H[node * D + lane * 4] = acc;
}

// ---------------- mean-pool + linear head + relu ---------------------------
__global__ void k_pool(const int* __restrict__ batch,
                       const float* __restrict__ Wlin, const float* __restrict__ blin,
                       float* __restrict__ out) {
    const float* H2 = g_H2;
    int g = blockIdx.x;
    int c = threadIdx.x;   // 128 threads
    int lo = 0, hi = N_NODES;
    while (lo < hi) { int m = (lo + hi) >> 1; if (batch[m] < g) lo = m + 1; else hi = m; }
    int start = lo;
    lo = 0; hi = N_NODES;
    while (lo < hi) { int m = (lo + hi) >> 1; if (batch[m] < g + 1) lo = m + 1; else hi = m; }
    int end = lo;

    float acc = 0.f;
    for (int n = start; n < end; n++) acc += H2[n * D + c];
    float cnt = (float)(end - start);
    float pooled = acc / fmaxf(cnt, 1.f);
    float v = pooled * Wlin[c];

    __shared__ float red[128];
    red[c] = v;
    __syncthreads();
    for (int s = 64; s > 0; s >>= 1) {
        if (c < s) red[c] += red[c + s];
        __syncthreads();
    }
    if (c == 0) out[g] = fmaxf(red[0] + blin[0], 0.f);
}

// ---------------- launch ---------------------------------------------------
extern "C" void kernel_launch(void* const* d_in, const int* in_sizes, int n_in,
                              void* d_out, int out_size) {
    const float* x      = (const float*)d_in[0];
    const int*   ei     = (const int*)d_in[1];
    const int*   batch  = (const int*)d_in[2];
    const float* ew     = (const float*)d_in[3];
    const float* W1_rel = (const float*)d_in[4];
    const float* b1     = (const float*)d_in[5];
    const float* W1_root= (const float*)d_in[6];
    const float* W3_rel = (const float*)d_in[7];
    const float* b3     = (const float*)d_in[8];
    const float* W3_root= (const float*)d_in[9];
    const float* Wlin   = (const float*)d_in[10];
    const float* blin   = (const float*)d_in[11];
    float*       out    = (float*)d_out;

    // CSR build
    k_zero<<<(N_NODES + 255) / 256, 256>>>();
    k_hist<<<(N_EDGES + 255) / 256, 256>>>(ei);
    k_scan<<<1, 1024>>>();
    k_place<<<(N_EDGES / 4 + 255) / 256, 256>>>(ei, ew);

    int gb = (N_NODES + 63) / 64;
    // layer 1
    k_gemm2<0><<<gb, 256>>>(x, W1_rel, W1_root, b1);
    k_agg<1><<<(N_NODES * 32 + 255) / 256, 256>>>();

    // layer 2
    k_gemm2<1><<<gb, 256>>>(nullptr, W3_rel, W3_root, b3);
    k_agg<2><<<(N_NODES * 32 + 255) / 256, 256>>>();

    // pool + head
    k_pool<<<NGRAPH, 128>>>(batch, Wlin, blin, out);
}

// round 9
// speedup vs baseline: 1.2902x; 1.1262x over previous
#include <cuda_runtime.h>

#define N_NODES 20000
#define N_EDGES 640000
#define D       128
#define NGRAPH  64

// ---------------- scratch (device globals) ---------------------------------
__device__ float g_Y [N_NODES * D];
__device__ float g_H [N_NODES * D];
__device__ float g_H2[N_NODES * D];
__device__ int   g_deg[N_NODES];
__device__ int   g_off[N_NODES + 1];
__device__ int   g_rank[N_EDGES];       // rank of edge within its dst bucket
__device__ int2  g_srcw[N_EDGES];       // packed (src, bit-cast weight)

// ---------------- CSR build ------------------------------------------------
__global__ void k_zero() {
    int i = blockIdx.x * blockDim.x + threadIdx.x;
    if (i < N_NODES) g_deg[i] = 0;
}

// 1 edge/thread (max warp count hides ATOMG latency); rank captured here
__global__ void k_hist(const int* __restrict__ ei) {
    int e = blockIdx.x * blockDim.x + threadIdx.x;
    if (e < N_EDGES) {
        int dst = ei[N_EDGES + e];
        g_rank[e] = atomicAdd(&g_deg[dst], 1);
    }
}

__global__ void k_scan() {
    __shared__ int sums[1024];
    const int CH = 20;
    int t = threadIdx.x;
    int base = t * CH;
    int local[CH];
    int s = 0;
    #pragma unroll
    for (int i = 0; i < CH; i++) {
        int idx = base + i;
        int v = (idx < N_NODES) ? g_deg[idx] : 0;
        local[i] = s;
        s += v;
    }
    sums[t] = s;
    __syncthreads();
    for (int d = 1; d < 1024; d <<= 1) {
        int v = 0;
        if (t >= d) v = sums[t - d];
        __syncthreads();
        if (t >= d) sums[t] += v;
        __syncthreads();
    }
    int off = (t == 0) ? 0 : sums[t - 1];
    #pragma unroll
    for (int i = 0; i < CH; i++) {
        int idx = base + i;
        if (idx < N_NODES) g_off[idx] = off + local[i];
    }
    if (t == 1023) g_off[N_NODES] = sums[1023];
}

// atomic-free scatter: p = off[dst] + rank[e]; 4 edges/thread for MLP
__global__ void k_place(const int* __restrict__ ei, const float* __restrict__ ew) {
    int e0 = (blockIdx.x * blockDim.x + threadIdx.x) * 4;
    if (e0 < N_EDGES) {
        int4   dd = *(const int4*)&ei[N_EDGES + e0];
        int4   ss = *(const int4*)&ei[e0];
        float4 ww = *(const float4*)&ew[e0];
        int4   rr = *(const int4*)&g_rank[e0];
        int p0 = g_off[dd.x] + rr.x;
        int p1 = g_off[dd.y] + rr.y;
        int p2 = g_off[dd.z] + rr.z;
        int p3 = g_off[dd.w] + rr.w;
        g_srcw[p0] = make_int2(ss.x, __float_as_int(ww.x));
        g_srcw[p1] = make_int2(ss.y, __float_as_int(ww.y));
        g_srcw[p2] = make_int2(ss.z, __float_as_int(ww.z));
        g_srcw[p3] = make_int2(ss.w, __float_as_int(ww.w));
    }
}

// ---------------- fused dual GEMM with packed f32x2 FFMA -------------------
__device__ __forceinline__ void ffma2(unsigned long long& d,
                                      unsigned long long a,
                                      unsigned long long b) {
    asm("fma.rn.f32x2 %0, %1, %2, %0;" : "+l"(d) : "l"(a), "l"(b));
}
__device__ __forceinline__ unsigned long long bcast2(float x) {
    unsigned long long r;
    asm("mov.b64 %0, {%1, %1};" : "=l"(r) : "f"(x));
    return r;
}

#define XS_STRIDE 36

template <int LAYER>   // 0: x -> (g_Y, g_H) | 1: g_H -> (g_Y, g_H2)
__global__ void __launch_bounds__(256, 2)
k_gemm2(const float* __restrict__ Xext,
        const float* __restrict__ Wa,
        const float* __restrict__ Wb,
        const float* __restrict__ bias) {
    const float* X  = (LAYER == 0) ? Xext : g_H;
    float* Ya = g_Y;
    float* Yb = (LAYER == 0) ? g_H : g_H2;

    __shared__ float Xs [64 * XS_STRIDE];   // [row][k]
    __shared__ float Was[32 * 128];         // [k][c]
    __shared__ float Wbs[32 * 128];         // [k][c]

    int tid = threadIdx.x;
    int tx = tid & 15, ty = tid >> 4;
    int row0 = blockIdx.x * 64;

    unsigned long long accA[4][4], accB[4][4];   // [r][colpair]
    #pragma unroll
    for (int r = 0; r < 4; r++)
        #pragma unroll
        for (int p = 0; p < 4; p++) { accA[r][p] = 0ull; accB[r][p] = 0ull; }

    for (int kt = 0; kt < 4; kt++) {
        int k0 = kt * 32;
        for (int i = tid; i < 64 * 8; i += 256) {
            int r = i >> 3, kk = i & 7;
            int gr = row0 + r;
            float4 v = make_float4(0.f, 0.f, 0.f, 0.f);
            if (gr < N_NODES) v = *(const float4*)&X[gr * D + k0 + kk * 4];
            *(float4*)&Xs[r * XS_STRIDE + kk * 4] = v;
        }
        {
            int c = tid & 127, half = tid >> 7;
            #pragma unroll
            for (int q = 0; q < 4; q++) {
                int kk4 = half * 4 + q;               // 0..7 covers full 32-k slice
                float4 va = *(const float4*)&Wa[c * D + k0 + kk4 * 4];
                float4 vb = *(const float4*)&Wb[c * D + k0 + kk4 * 4];
                Was[(kk4 * 4 + 0) * 128 + c] = va.x;
                Was[(kk4 * 4 + 1) * 128 + c] = va.y;
                Was[(kk4 * 4 + 2) * 128 + c] = va.z;
                Was[(kk4 * 4 + 3) * 128 + c] = va.w;
                Wbs[(kk4 * 4 + 0) * 128 + c] = vb.x;
                Wbs[(kk4 * 4 + 1) * 128 + c] = vb.y;
                Wbs[(kk4 * 4 + 2) * 128 + c] = vb.z;
                Wbs[(kk4 * 4 + 3) * 128 + c] = vb.w;
            }
        }
        __syncthreads();

        #pragma unroll
        for (int kk4 = 0; kk4 < 8; kk4++) {
            float4 xr[4];
            #pragma unroll
            for (int r = 0; r < 4; r++)
                xr[r] = *(float4*)&Xs[(ty * 4 + r) * XS_STRIDE + kk4 * 4];

            #define K_STEP(J, COMP)                                                        \
            {                                                                              \
                int kk = kk4 * 4 + J;                                                      \
                unsigned long long xx[4];                                                  \
                xx[0] = bcast2(xr[0].COMP); xx[1] = bcast2(xr[1].COMP);                    \
                xx[2] = bcast2(xr[2].COMP); xx[3] = bcast2(xr[3].COMP);                    \
                _Pragma("unroll")                                                          \
                for (int p = 0; p < 4; p++) {                                              \
                    unsigned long long wa = *(const unsigned long long*)&Was[kk * 128 + 32 * p + 2 * tx]; \
                    unsigned long long wb = *(const unsigned long long*)&Wbs[kk * 128 + 32 * p + 2 * tx]; \
                    _Pragma("unroll")                                                      \
                    for (int r = 0; r < 4; r++) {                                          \
                        ffma2(accA[r][p], xx[r], wa);                                      \
                        ffma2(accB[r][p], xx[r], wb);                                      \
                    }                                                                      \
                }                                                                          \
            }
            K_STEP(0, x)
            K_STEP(1, y)
            K_STEP(2, z)
            K_STEP(3, w)
            #undef K_STEP
        }
        __syncthreads();
    }

    #pragma unroll
    for (int p = 0; p < 4; p++) {
        int c = 32 * p + 2 * tx;
        float b0 = bias[c], b1 = bias[c + 1];
        #pragma unroll
        for (int r = 0; r < 4; r++) {
            int gr = row0 + ty * 4 + r;
            if (gr < N_NODES) {
                float a0, a1;
                asm("mov.b64 {%0, %1}, %2;" : "=f"(a0), "=f"(a1) : "l"(accA[r][p]));
                *(float2*)&Ya[gr * D + c] = make_float2(a0, a1);
                asm("mov.b64 {%0, %1}, %2;" : "=f"(a0), "=f"(a1) : "l"(accB[r][p]));
                *(float2*)&Yb[gr * D + c] = make_float2(a0 + b0, a1 + b1);
            }
        }
    }
}

// ---------------- edge aggregation: H[i] += sum_e w_e * Y[src_e] -----------
template <int MODE>   // 1: into g_H with relu; 2: into g_H2
__global__ void k_agg() {
    const float* Y = g_Y;
    float* H = (MODE == 1) ? g_H : g_H2;
    int node = (blockIdx.x * blockDim.x + threadIdx.x) >> 5;
    int lane = threadIdx.x & 31;
    if (node >= N_NODES) return;
    int beg = g_off[node], end = g_off[node + 1];
    float4 acc = *(float4*)&H[node * D + lane * 4];
    int e = beg;
    for (; e + 8 <= end; e += 8) {
        int2 p[8];
        #pragma unroll
        for (int j = 0; j < 8; j++) p[j] = g_srcw[e + j];
        float4 v[8];
        #pragma unroll
        for (int j = 0; j < 8; j++) v[j] = *(const float4*)&Y[p[j].x * D + lane * 4];
        #pragma unroll
        for (int j = 0; j < 8; j++) {
            float w = __int_as_float(p[j].y);
            acc.x += w * v[j].x; acc.y += w * v[j].y;
            acc.z += w * v[j].z; acc.w += w * v[j].w;
        }
    }
    for (; e < end; e++) {
        int2 pe = g_srcw[e];
        float w = __int_as_float(pe.y);
        float4 v = *(const float4*)&Y[pe.x * D + lane * 4];
        acc.x += w * v.x; acc.y += w * v.y; acc.z += w * v.z; acc.w += w * v.w;
    }
    if (MODE == 1) {
        acc.x = fmaxf(acc.x, 0.f); acc.y = fmaxf(acc.y, 0.f);
        acc.z = fmaxf(acc.z, 0.f); acc.w = fmaxf(acc.w, 0.f);
    }
    *(float4*)&H[node * D + lane * 4] = acc;
}

// ---------------- mean-pool + linear head + relu ---------------------------
__global__ void k_pool(const int* __restrict__ batch,
                       const float* __restrict__ Wlin, const float* __restrict__ blin,
                       float* __restrict__ out) {
    const float* H2 = g_H2;
    int g = blockIdx.x;
    int c = threadIdx.x;   // 128 threads
    int lo = 0, hi = N_NODES;
    while (lo < hi) { int m = (lo + hi) >> 1; if (batch[m] < g) lo = m + 1; else hi = m; }
    int start = lo;
    lo = 0; hi = N_NODES;
    while (lo < hi) { int m = (lo + hi) >> 1; if (batch[m] < g + 1) lo = m + 1; else hi = m; }
    int end = lo;

    float acc = 0.f;
    for (int n = start; n < end; n++) acc += H2[n * D + c];
    float cnt = (float)(end - start);
    float pooled = acc / fmaxf(cnt, 1.f);
    float v = pooled * Wlin[c];

    __shared__ float red[128];
    red[c] = v;
    __syncthreads();
    for (int s = 64; s > 0; s >>= 1) {
        if (c < s) red[c] += red[c + s];
        __syncthreads();
    }
    if (c == 0) out[g] = fmaxf(red[0] + blin[0], 0.f);
}

// ---------------- launch ---------------------------------------------------
// CSR build (edges only) and layer-1 GEMM (x only) are independent:
// express that in the captured graph via the standard fork/join event pattern
// so graph exec runs them concurrently.
extern "C" void kernel_launch(void* const* d_in, const int* in_sizes, int n_in,
                              void* d_out, int out_size) {
    const float* x      = (const float*)d_in[0];
    const int*   ei     = (const int*)d_in[1];
    const int*   batch  = (const int*)d_in[2];
    const float* ew     = (const float*)d_in[3];
    const float* W1_rel = (const float*)d_in[4];
    const float* b1     = (const float*)d_in[5];
    const float* W1_root= (const float*)d_in[6];
    const float* W3_rel = (const float*)d_in[7];
    const float* b3     = (const float*)d_in[8];
    const float* W3_root= (const float*)d_in[9];
    const float* Wlin   = (const float*)d_in[10];
    const float* blin   = (const float*)d_in[11];
    float*       out    = (float*)d_out;

    int gb = (N_NODES + 63) / 64;

    cudaStream_t side = nullptr;
    cudaEvent_t evFork = nullptr, evJoin = nullptr;
    bool forked = (cudaStreamCreateWithFlags(&side, cudaStreamNonBlocking) == cudaSuccess) &&
                  (cudaEventCreateWithFlags(&evFork, cudaEventDisableTiming) == cudaSuccess) &&
                  (cudaEventCreateWithFlags(&evJoin, cudaEventDisableTiming) == cudaSuccess);

    if (forked && cudaEventRecord(evFork, 0) == cudaSuccess &&
        cudaStreamWaitEvent(side, evFork, 0) == cudaSuccess) {
        // Branch A (main stream): layer-1 dual GEMM
        k_gemm2<0><<<gb, 256>>>(x, W1_rel, W1_root, b1);
        // Branch B (side stream): CSR build
        k_zero <<<(N_NODES + 255) / 256, 256, 0, side>>>();
        k_hist <<<(N_EDGES + 255) / 256, 256, 0, side>>>(ei);
        k_scan <<<1, 1024, 0, side>>>();
        k_place<<<(N_EDGES / 4 + 255) / 256, 256, 0, side>>>(ei, ew);
        // Join back onto main stream
        cudaEventRecord(evJoin, side);
        cudaStreamWaitEvent(0, evJoin, 0);
    } else {
        // Serial fallback (identical to R8)
        k_zero <<<(N_NODES + 255) / 256, 256>>>();
        k_hist <<<(N_EDGES + 255) / 256, 256>>>(ei);
        k_scan <<<1, 1024>>>();
        k_place<<<(N_EDGES / 4 + 255) / 256, 256>>>(ei, ew);
        k_gemm2<0><<<gb, 256>>>(x, W1_rel, W1_root, b1);
    }

    // layer 1 aggregation (needs CSR + gemm1)
    k_agg<1><<<(N_NODES * 32 + 255) / 256, 256>>>();

    // layer 2
    k_gemm2<1><<<gb, 256>>>(nullptr, W3_rel, W3_root, b3);
    k_agg<2><<<(N_NODES * 32 + 255) / 256, 256>>>();

    // pool + head
    k_pool<<<NGRAPH, 128>>>(batch, Wlin, blin, out);
}